// round 2
// baseline (speedup 1.0000x reference)
#include <cuda_runtime.h>
#include <cuda_bf16.h>
#include <math.h>

// GramSchmidt: x[8,32,128,1024] fp32.
// q_i = x_i - sum_{j<i} (x_i.q_j / q_j.q_j) q_j ; out = q / ||q||_over-N-axis
// Reformulated via Gram matrix: G = X X^T (per bc), L lower-tri recurrence,
// Q = L X, out = Q * rsqrt(colsumsq(Q)).

#define NBC 256          // 8*32 independent problems
#define NV  128          // vectors per problem
#define DD  1024         // dim

__device__ float g_G[NBC * NV * NV];   // 16 MB scratch
__device__ float g_L[NBC * NV * NV];   // 16 MB scratch

// ---------------------------------------------------------------- kernel A
// G[bc] = X[bc] @ X[bc]^T   (128x128 from 128x1024), 256 thr, 8x8 per thread
__global__ void gs_gram_kernel(const float* __restrict__ X) {
    extern __shared__ float4 sm4[];          // Xs4[128][32] swizzled
    const int bc = blockIdx.x;
    const float* Xb = X + (size_t)bc * (NV * DD);
    const int t  = threadIdx.x;
    const int tx = t & 15;
    const int ty = t >> 4;

    float acc[8][8];
#pragma unroll
    for (int m = 0; m < 8; m++)
#pragma unroll
        for (int n = 0; n < 8; n++) acc[m][n] = 0.f;

    for (int ch = 0; ch < 8; ch++) {
        __syncthreads();
        // load 128 rows x 128 cols chunk, swizzle col4 by (row>>3)
#pragma unroll
        for (int it = 0; it < 16; it++) {
            int fl = t + 256 * it;           // 0..4095
            int r  = fl >> 5;
            int c4 = fl & 31;
            float4 v = *(const float4*)(Xb + r * DD + ch * 128 + c4 * 4);
            sm4[r * 32 + ((c4 + (r >> 3)) & 31)] = v;
        }
        __syncthreads();
#pragma unroll 4
        for (int k4 = 0; k4 < 32; k4++) {
            float4 a4[8], b4[8];
#pragma unroll
            for (int m = 0; m < 8; m++) a4[m] = sm4[(ty * 8 + m) * 32 + ((k4 + ty) & 31)];
#pragma unroll
            for (int n = 0; n < 8; n++) b4[n] = sm4[(tx * 8 + n) * 32 + ((k4 + tx) & 31)];
#pragma unroll
            for (int m = 0; m < 8; m++)
#pragma unroll
                for (int n = 0; n < 8; n++) {
                    acc[m][n] += a4[m].x * b4[n].x;
                    acc[m][n] += a4[m].y * b4[n].y;
                    acc[m][n] += a4[m].z * b4[n].z;
                    acc[m][n] += a4[m].w * b4[n].w;
                }
        }
    }
    float* Gb = g_G + (size_t)bc * (NV * NV);
#pragma unroll
    for (int m = 0; m < 8; m++)
#pragma unroll
        for (int n4 = 0; n4 < 2; n4++) {
            float4 v = make_float4(acc[m][n4 * 4 + 0], acc[m][n4 * 4 + 1],
                                   acc[m][n4 * 4 + 2], acc[m][n4 * 4 + 3]);
            *(float4*)(Gb + (ty * 8 + m) * NV + tx * 8 + n4 * 4) = v;
        }
}

// ---------------------------------------------------------------- kernel B
// Recurrence in coefficient space. 128 threads per CTA, one CTA per bc.
//   c_j  = sum_{k<=j} L[j][k] * G[k][i]         (thread j, j<i)
//   coef = c_j / n_j ;  n_i = G[i][i] - sum coef_j*c_j  (Pythagoras)
//   L[i][k] = delta_ik - sum_{j<i} coef_j L[j][k]
__global__ void gs_chol_kernel() {
    extern __shared__ float sm[];
    float* Gs   = sm;                      // 128*128
    float* Ls   = Gs + NV * NV;            // 128*129 (pad -> conflict-free col reads)
    float* coef = Ls + NV * 129;           // 128
    float* red  = coef + NV;               // 128
    float* nn   = red + NV;                // 128

    const int bc = blockIdx.x;
    const int t  = threadIdx.x;            // 128 threads
    const float* Gb = g_G + (size_t)bc * (NV * NV);

#pragma unroll
    for (int it = 0; it < 32; it++) {      // 16384 floats as 4096 float4
        int fl = t + 128 * it;
        ((float4*)Gs)[fl] = ((const float4*)Gb)[fl];
    }
#pragma unroll
    for (int it = 0; it < 129; it++) Ls[t + 128 * it] = 0.f;
    __syncthreads();
    if (t == 0) { Ls[0] = 1.f; nn[0] = Gs[0]; }
    __syncthreads();

    for (int i = 1; i < NV; i++) {
        // phase A: dots + coefficients
        if (t < i) {
            const float* Lr = Ls + t * 129;
            float s = 0.f;
            for (int k = 0; k <= t; k++) s += Lr[k] * Gs[k * NV + i];
            float cf = s / nn[t];
            coef[t] = cf;
            red[t]  = cf * s;
        }
        __syncthreads();
        // phase B: new L row (+ norm of new q on a spare thread)
        if (t <= i) {
            float s = (t == i) ? 1.f : 0.f;
            for (int j = 0; j < i; j++) s -= coef[j] * Ls[j * 129 + t];
            Ls[i * 129 + t] = s;
        } else if (t == 127) {
            float s = Gs[i * NV + i];
            for (int j = 0; j < i; j++) s -= red[j];
            nn[i] = s;
        }
        __syncthreads();
    }

    float* Lb = g_L + (size_t)bc * (NV * NV);
#pragma unroll 4
    for (int it = 0; it < 128; it++) {
        int fl = t + 128 * it;             // 0..16383
        int r = fl >> 7, k = fl & 127;
        Lb[fl] = Ls[r * 129 + k];
    }
}

// ---------------------------------------------------------------- kernel C
// Q = L @ Xchunk (triangular), then column sum-of-squares over N, scale, store.
// 2048 CTAs: blockIdx = bc*8 + dchunk. 256 threads, 8x8 per thread.
__global__ void gs_apply_kernel(const float* __restrict__ X, float* __restrict__ out) {
    extern __shared__ float smf[];
    float4* Ls4 = (float4*)smf;            // 128*32 float4 swizzled (64KB)
    float*  Xc  = smf + NV * NV;           // 128 k-rows x 128 d-cols (64KB)
    float*  rn  = Xc + NV * NV;            // 128

    const int bc = blockIdx.x >> 3;
    const int dc = blockIdx.x & 7;
    const int t  = threadIdx.x;
    const int tx = t & 15;
    const int ty = t >> 4;

    const float* Xb = X + (size_t)bc * (NV * DD) + dc * 128;
    const float* Lb = g_L + (size_t)bc * (NV * NV);

#pragma unroll
    for (int it = 0; it < 16; it++) {
        int fl = t + 256 * it;
        int r = fl >> 5, k4 = fl & 31;
        float4 v = ((const float4*)Lb)[r * 32 + k4];
        Ls4[r * 32 + ((k4 + (r >> 3)) & 31)] = v;
    }
#pragma unroll
    for (int it = 0; it < 16; it++) {
        int fl = t + 256 * it;
        int r = fl >> 5, c4 = fl & 31;
        *(float4*)(Xc + r * 128 + c4 * 4) = *(const float4*)(Xb + r * DD + c4 * 4);
    }
    __syncthreads();

    float acc[8][8];
#pragma unroll
    for (int m = 0; m < 8; m++)
#pragma unroll
        for (int n = 0; n < 8; n++) acc[m][n] = 0.f;

    const int kmax4 = 2 * ty + 2;          // rows ty*8..ty*8+7 need k <= ty*8+7
    for (int k4 = 0; k4 < kmax4; k4++) {
        float4 a4[8];
#pragma unroll
        for (int m = 0; m < 8; m++) a4[m] = Ls4[(ty * 8 + m) * 32 + ((k4 + ty) & 31)];
#pragma unroll
        for (int kk = 0; kk < 4; kk++) {
            const float* xr = Xc + (k4 * 4 + kk) * 128 + tx * 8;
            float4 b0 = *(const float4*)xr;
            float4 b1 = *(const float4*)(xr + 4);
            float bb[8] = {b0.x, b0.y, b0.z, b0.w, b1.x, b1.y, b1.z, b1.w};
#pragma unroll
            for (int m = 0; m < 8; m++) {
                float av = (kk == 0) ? a4[m].x : (kk == 1) ? a4[m].y
                         : (kk == 2) ? a4[m].z : a4[m].w;
#pragma unroll
                for (int n = 0; n < 8; n++) acc[m][n] += av * bb[n];
            }
        }
    }
    __syncthreads();                        // everyone done reading Ls4

    float* Qs = smf;                        // reuse L region as Q staging
#pragma unroll
    for (int m = 0; m < 8; m++) {
        *(float4*)(Qs + (ty * 8 + m) * 128 + tx * 8) =
            make_float4(acc[m][0], acc[m][1], acc[m][2], acc[m][3]);
        *(float4*)(Qs + (ty * 8 + m) * 128 + tx * 8 + 4) =
            make_float4(acc[m][4], acc[m][5], acc[m][6], acc[m][7]);
    }
    __syncthreads();

    if (t < 128) {
        float s = 0.f;
#pragma unroll 4
        for (int i = 0; i < 128; i++) { float q = Qs[i * 128 + t]; s += q * q; }
        rn[t] = rsqrtf(s);
    }
    __syncthreads();

    float* ob = out + (size_t)bc * (NV * DD) + dc * 128;
#pragma unroll
    for (int it = 0; it < 16; it++) {
        int fl = t + 256 * it;
        int r = fl >> 5, c4 = fl & 31;
        float4 q = *(float4*)(Qs + r * 128 + c4 * 4);
        q.x *= rn[c4 * 4 + 0];
        q.y *= rn[c4 * 4 + 1];
        q.z *= rn[c4 * 4 + 2];
        q.w *= rn[c4 * 4 + 3];
        *(float4*)(ob + r * DD + c4 * 4) = q;
    }
}

// ---------------------------------------------------------------- launcher
extern "C" void kernel_launch(void* const* d_in, const int* in_sizes, int n_in,
                              void* d_out, int out_size) {
    const float* x = (const float*)d_in[0];
    float* out = (float*)d_out;

    const int smA = 128 * 32 * (int)sizeof(float4);                  // 65536
    const int smB = (NV * NV + NV * 129 + 3 * NV) * (int)sizeof(float); // 133120
    const int smC = (NV * NV * 2 + NV) * (int)sizeof(float);         // 131584

    cudaFuncSetAttribute(gs_gram_kernel,  cudaFuncAttributeMaxDynamicSharedMemorySize, smA);
    cudaFuncSetAttribute(gs_chol_kernel,  cudaFuncAttributeMaxDynamicSharedMemorySize, smB);
    cudaFuncSetAttribute(gs_apply_kernel, cudaFuncAttributeMaxDynamicSharedMemorySize, smC);

    gs_gram_kernel<<<NBC, 256, smA>>>(x);
    gs_chol_kernel<<<NBC, 128, smB>>>();
    gs_apply_kernel<<<NBC * 8, 256, smC>>>(x, out);
}

// round 4
// speedup vs baseline: 1.3967x; 1.3967x over previous
#include <cuda_runtime.h>
#include <cuda_bf16.h>
#include <stdint.h>
#include <math.h>

// GramSchmidt: x[8,32,128,1024] fp32.
// G = X X^T per (b,c); L lower-tri CGS recurrence in Gram space; Q = L X;
// out = Q * rsqrt(colsumsq_over_N(Q)).

#define NBC 256
#define NV  128
#define DD  1024

__device__ float g_G[NBC * NV * NV];
__device__ float g_L[NBC * NV * NV];

__device__ __forceinline__ void cp_async16(uint32_t sa, const void* g) {
    asm volatile("cp.async.cg.shared.global [%0], [%1], 16;\n" :: "r"(sa), "l"(g));
}
#define CP_COMMIT()  asm volatile("cp.async.commit_group;\n" ::: "memory")
#define CP_WAIT(n)   asm volatile("cp.async.wait_group %0;\n" :: "n"(n) : "memory")

__device__ __forceinline__ void fma2(unsigned long long& d,
                                     unsigned long long a, unsigned long long b) {
    asm volatile("fma.rn.f32x2 %0, %1, %2, %0;" : "+l"(d) : "l"(a), "l"(b));
}

// ---------------------------------------------------------------- kernel A
// G[bc] = X X^T. 256 thr, 8x8/thread, f32x2 FMA (pairs over k), cp.async
// double-buffered chunks of 64 cols.
__global__ void gs_gram_kernel(const float* __restrict__ X) {
    extern __shared__ float4 sm4[];               // 2 x [128 rows][16 f4] swizzled
    const int bc = blockIdx.x;
    const float* Xb = X + (size_t)bc * (NV * DD);
    const int t  = threadIdx.x;
    const int tx = t & 15;
    const int ty = t >> 4;
    const uint32_t sbase = (uint32_t)__cvta_generic_to_shared(sm4);

    unsigned long long acc[8][8];
#pragma unroll
    for (int m = 0; m < 8; m++)
#pragma unroll
        for (int n = 0; n < 8; n++) acc[m][n] = 0ull;

    // prologue: chunk 0
    {
#pragma unroll
        for (int it = 0; it < 8; it++) {
            int fl = t + 256 * it;                // 0..2047
            int r = fl >> 4, c4 = fl & 15;
            cp_async16(sbase + (uint32_t)((r * 16 + ((c4 + (r >> 3)) & 15)) * 16),
                       Xb + r * DD + c4 * 4);
        }
        CP_COMMIT();
    }

    for (int ch = 0; ch < 16; ch++) {
        if (ch + 1 < 16) {
            int buf = (ch + 1) & 1;
#pragma unroll
            for (int it = 0; it < 8; it++) {
                int fl = t + 256 * it;
                int r = fl >> 4, c4 = fl & 15;
                cp_async16(sbase + (uint32_t)((buf * 2048 + r * 16 + ((c4 + (r >> 3)) & 15)) * 16),
                           Xb + r * DD + (ch + 1) * 64 + c4 * 4);
            }
            CP_COMMIT();
            CP_WAIT(1);
        } else {
            CP_WAIT(0);
        }
        __syncthreads();                           // chunk ch visible to all

        const uint32_t cb = sbase + (uint32_t)((ch & 1) * 2048) * 16;
#pragma unroll
        for (int k4 = 0; k4 < 16; k4++) {
            unsigned long long a2[8][2], b2[8][2];
#pragma unroll
            for (int m = 0; m < 8; m++) {
                int r = ty * 8 + m;
                uint32_t sa = cb + (uint32_t)((r * 16 + ((k4 + ty) & 15)) * 16);
                asm volatile("ld.shared.v2.u64 {%0,%1}, [%2];"
                             : "=l"(a2[m][0]), "=l"(a2[m][1]) : "r"(sa));
            }
#pragma unroll
            for (int n = 0; n < 8; n++) {
                int r = tx * 8 + n;
                uint32_t sa = cb + (uint32_t)((r * 16 + ((k4 + tx) & 15)) * 16);
                asm volatile("ld.shared.v2.u64 {%0,%1}, [%2];"
                             : "=l"(b2[n][0]), "=l"(b2[n][1]) : "r"(sa));
            }
#pragma unroll
            for (int m = 0; m < 8; m++)
#pragma unroll
                for (int n = 0; n < 8; n++) {
                    fma2(acc[m][n], a2[m][0], b2[n][0]);
                    fma2(acc[m][n], a2[m][1], b2[n][1]);
                }
        }
        __syncthreads();                           // done reading buf before reuse
    }

    float* Gb = g_G + (size_t)bc * (NV * NV);
#pragma unroll
    for (int m = 0; m < 8; m++) {
        float v[8];
#pragma unroll
        for (int n = 0; n < 8; n++) {
            float lo, hi;
            asm volatile("mov.b64 {%0,%1}, %2;" : "=f"(lo), "=f"(hi) : "l"(acc[m][n]));
            v[n] = lo + hi;
        }
        *(float4*)(Gb + (ty * 8 + m) * NV + tx * 8)     = make_float4(v[0], v[1], v[2], v[3]);
        *(float4*)(Gb + (ty * 8 + m) * NV + tx * 8 + 4) = make_float4(v[4], v[5], v[6], v[7]);
    }
}

// ---------------------------------------------------------------- kernel B
// Recurrence. 128 thr/CTA, L padded to stride 132, G streamed one row/iter
// (G symmetric: G[k][i] = row-i element k). Fixed-length unrollable loops:
// zero-padded L rows and coef make out-of-range terms exact no-ops.
__global__ void gs_chol_kernel() {
    extern __shared__ float sm[];
    float* Ls   = sm;                  // 128 x 132
    float* gr   = Ls + NV * 132;       // 128 (G row i)
    float* coef = gr + NV;             // 128
    float* red  = coef + NV;           // 128
    float* nn   = red + NV;            // 128

    const int bc = blockIdx.x;
    const int t  = threadIdx.x;        // 128
    const int w  = t >> 5;
    const float* Gb = g_G + (size_t)bc * (NV * NV);

#pragma unroll
    for (int i4 = 0; i4 < 33; i4++)
        *(float4*)(Ls + t * 132 + i4 * 4) = make_float4(0.f, 0.f, 0.f, 0.f);
    nn[t] = 1.f; coef[t] = 0.f; red[t] = 0.f;
    __syncthreads();
    if (t == 0) { Ls[0] = 1.f; nn[0] = Gb[0]; }
    __syncthreads();

    for (int i = 1; i < NV; i++) {
        if (t < 32) ((float4*)gr)[t] = ((const float4*)(Gb + i * NV))[t];
        __syncthreads();

        // phase A: s_t = sum_k L[t][k] * G[i][k]   (rows >= i are all-zero)
        const float* Lr = Ls + t * 132;
        float s = 0.f;
        const int kmax = 32 * (w + 1);             // warp-uniform triangular bound
        for (int k0 = 0; k0 < kmax; k0 += 32) {
            float s0 = 0.f, s1 = 0.f, s2 = 0.f, s3 = 0.f;
#pragma unroll
            for (int k = 0; k < 32; k += 4) {
                s0 += Lr[k0 + k + 0] * gr[k0 + k + 0];
                s1 += Lr[k0 + k + 1] * gr[k0 + k + 1];
                s2 += Lr[k0 + k + 2] * gr[k0 + k + 2];
                s3 += Lr[k0 + k + 3] * gr[k0 + k + 3];
            }
            s += (s0 + s1) + (s2 + s3);
        }
        float cf = (t < i) ? (s / nn[t]) : 0.f;
        coef[t] = cf;
        red[t]  = cf * s;
        __syncthreads();

        // phase B: L[i][t] = delta(i,t) - sum_j coef[j] * L[j][t]
        float b0 = 0.f, b1 = 0.f, b2 = 0.f, b3 = 0.f;
        const int jmax = (i + 31) & ~31;           // coef[j>=i] == 0
        for (int j0 = 0; j0 < jmax; j0 += 32) {
#pragma unroll
            for (int j = 0; j < 32; j += 4) {
                b0 += coef[j0 + j + 0] * Ls[(j0 + j + 0) * 132 + t];
                b1 += coef[j0 + j + 1] * Ls[(j0 + j + 1) * 132 + t];
                b2 += coef[j0 + j + 2] * Ls[(j0 + j + 2) * 132 + t];
                b3 += coef[j0 + j + 3] * Ls[(j0 + j + 3) * 132 + t];
            }
        }
        Ls[i * 132 + t] = ((t == i) ? 1.f : 0.f) - ((b0 + b1) + (b2 + b3));
        if (t == 127) {                            // n_i = G[i][i] - sum coef*dot
            float sn = gr[i];
#pragma unroll 4
            for (int j = 0; j < NV; j++) sn -= red[j];
            nn[i] = sn;
        }
        __syncthreads();
    }

    float* Lb = g_L + (size_t)bc * (NV * NV);
#pragma unroll 4
    for (int it = 0; it < 32; it++) {
        int fl = t + 128 * it;                     // 0..4095 float4
        int r = fl >> 5, k4 = fl & 31;
        ((float4*)Lb)[fl] = *(float4*)(Ls + r * 132 + k4 * 4);
    }
}

// ---------------------------------------------------------------- kernel C
// Q = L @ Xchunk (triangular), f32x2 FMA (pairs over n), then column
// sum-of-squares over N, scale, store. blockIdx = bc*8 + dchunk.
__global__ void gs_apply_kernel(const float* __restrict__ X, float* __restrict__ out) {
    extern __shared__ float smf[];
    float4* Ls4 = (float4*)smf;            // 128 x 32 f4 swizzled
    float*  Xc  = smf + NV * NV;           // 128 k x 128 d
    float*  rn  = Xc + NV * NV;            // 128

    const int bc = blockIdx.x >> 3;
    const int dc = blockIdx.x & 7;
    const int t  = threadIdx.x;
    const int tx = t & 15;
    const int ty = t >> 4;
    const uint32_t sbase = (uint32_t)__cvta_generic_to_shared(smf);

    const float* Xb = X + (size_t)bc * (NV * DD) + dc * 128;
    const float* Lb = g_L + (size_t)bc * (NV * NV);

#pragma unroll
    for (int it = 0; it < 16; it++) {
        int fl = t + 256 * it;
        int r = fl >> 5, k4 = fl & 31;
        float4 v = ((const float4*)Lb)[r * 32 + k4];
        Ls4[r * 32 + ((k4 + (r >> 3)) & 31)] = v;
    }
#pragma unroll
    for (int it = 0; it < 16; it++) {
        int fl = t + 256 * it;
        int r = fl >> 5, c4 = fl & 31;
        *(float4*)(Xc + r * 128 + c4 * 4) = *(const float4*)(Xb + r * DD + c4 * 4);
    }
    __syncthreads();

    unsigned long long acc2[8][4];
#pragma unroll
    for (int m = 0; m < 8; m++)
#pragma unroll
        for (int p = 0; p < 4; p++) acc2[m][p] = 0ull;

    const int kmax4 = 2 * ty + 2;          // rows ty*8..ty*8+7 need k <= ty*8+7
    for (int k4 = 0; k4 < kmax4; k4++) {
        float4 a4[8];
#pragma unroll
        for (int m = 0; m < 8; m++) a4[m] = Ls4[(ty * 8 + m) * 32 + ((k4 + ty) & 31)];
#pragma unroll
        for (int kk = 0; kk < 4; kk++) {
            unsigned long long bp[4];
            uint32_t sa = sbase + (uint32_t)(NV * NV * 4) +
                          (uint32_t)(((k4 * 4 + kk) * 128 + tx * 8) * 4);
            asm volatile("ld.shared.v2.u64 {%0,%1}, [%2];"
                         : "=l"(bp[0]), "=l"(bp[1]) : "r"(sa));
            asm volatile("ld.shared.v2.u64 {%0,%1}, [%2];"
                         : "=l"(bp[2]), "=l"(bp[3]) : "r"(sa + 16));
#pragma unroll
            for (int m = 0; m < 8; m++) {
                float av = (kk == 0) ? a4[m].x : (kk == 1) ? a4[m].y
                         : (kk == 2) ? a4[m].z : a4[m].w;
                unsigned long long ap;
                asm volatile("mov.b64 %0, {%1,%1};" : "=l"(ap) : "f"(av));
                fma2(acc2[m][0], ap, bp[0]);
                fma2(acc2[m][1], ap, bp[1]);
                fma2(acc2[m][2], ap, bp[2]);
                fma2(acc2[m][3], ap, bp[3]);
            }
        }
    }
    __syncthreads();                        // everyone done reading Ls4

    float* Qs = smf;                        // reuse L region as Q staging
#pragma unroll
    for (int m = 0; m < 8; m++) {
        float v[8];
#pragma unroll
        for (int p = 0; p < 4; p++) {
            float lo, hi;
            asm volatile("mov.b64 {%0,%1}, %2;" : "=f"(lo), "=f"(hi) : "l"(acc2[m][p]));
            v[2 * p] = lo; v[2 * p + 1] = hi;
        }
        *(float4*)(Qs + (ty * 8 + m) * 128 + tx * 8)     = make_float4(v[0], v[1], v[2], v[3]);
        *(float4*)(Qs + (ty * 8 + m) * 128 + tx * 8 + 4) = make_float4(v[4], v[5], v[6], v[7]);
    }
    __syncthreads();

    if (t < 128) {
        float s = 0.f;
#pragma unroll 4
        for (int i = 0; i < 128; i++) { float q = Qs[i * 128 + t]; s += q * q; }
        rn[t] = rsqrtf(s);
    }
    __syncthreads();

    float* ob = out + (size_t)bc * (NV * DD) + dc * 128;
#pragma unroll
    for (int it = 0; it < 16; it++) {
        int fl = t + 256 * it;
        int r = fl >> 5, c4 = fl & 31;
        float4 q = *(float4*)(Qs + r * 128 + c4 * 4);
        q.x *= rn[c4 * 4 + 0];
        q.y *= rn[c4 * 4 + 1];
        q.z *= rn[c4 * 4 + 2];
        q.w *= rn[c4 * 4 + 3];
        *(float4*)(ob + r * DD + c4 * 4) = q;
    }
}

// ---------------------------------------------------------------- launcher
extern "C" void kernel_launch(void* const* d_in, const int* in_sizes, int n_in,
                              void* d_out, int out_size) {
    const float* x = (const float*)d_in[0];
    float* out = (float*)d_out;

    const int smA = 2 * 2048 * (int)sizeof(float4);                     // 65536
    const int smB = (NV * 132 + 4 * NV) * (int)sizeof(float);           // 69632
    const int smC = (NV * NV * 2 + NV) * (int)sizeof(float);            // 131584

    cudaFuncSetAttribute(gs_gram_kernel,  cudaFuncAttributeMaxDynamicSharedMemorySize, smA);
    cudaFuncSetAttribute(gs_chol_kernel,  cudaFuncAttributeMaxDynamicSharedMemorySize, smB);
    cudaFuncSetAttribute(gs_apply_kernel, cudaFuncAttributeMaxDynamicSharedMemorySize, smC);

    gs_gram_kernel<<<NBC, 256, smA>>>(x);
    gs_chol_kernel<<<NBC, 128, smB>>>();
    gs_apply_kernel<<<NBC * 8, 256, smC>>>(x, out);
}

// round 5
// speedup vs baseline: 1.7634x; 1.2625x over previous
#include <cuda_runtime.h>
#include <cuda_bf16.h>
#include <stdint.h>
#include <math.h>

// GramSchmidt: x[8,32,128,1024] fp32.
// G = X X^T per (b,c); L lower-tri CGS recurrence in Gram space; Q = L X;
// out = Q * rsqrt(colsumsq_over_N(Q)).

#define NBC 256
#define NV  128
#define DD  1024

__device__ float g_G[NBC * NV * NV];
__device__ float g_L[NBC * NV * NV];

__device__ __forceinline__ void cp_async16(uint32_t sa, const void* g) {
    asm volatile("cp.async.cg.shared.global [%0], [%1], 16;\n" :: "r"(sa), "l"(g));
}
#define CP_COMMIT()  asm volatile("cp.async.commit_group;\n" ::: "memory")
#define CP_WAIT(n)   asm volatile("cp.async.wait_group %0;\n" :: "n"(n) : "memory")

__device__ __forceinline__ void fma2(unsigned long long& d,
                                     unsigned long long a, unsigned long long b) {
    asm volatile("fma.rn.f32x2 %0, %1, %2, %0;" : "+l"(d) : "l"(a), "l"(b));
}

// ---------------------------------------------------------------- kernel A
// G[bc] = X X^T. 256 thr, 8x8/thread, f32x2 FMA (pairs over k), cp.async
// 3-stage ring of 64-col chunks.
__global__ void gs_gram_kernel(const float* __restrict__ X) {
    extern __shared__ float4 sm4[];               // 3 x [128 rows][16 f4] swizzled
    const int bc = blockIdx.x;
    const float* Xb = X + (size_t)bc * (NV * DD);
    const int t  = threadIdx.x;
    const int tx = t & 15;
    const int ty = t >> 4;
    const uint32_t sbase = (uint32_t)__cvta_generic_to_shared(sm4);

    unsigned long long acc[8][8];
#pragma unroll
    for (int m = 0; m < 8; m++)
#pragma unroll
        for (int n = 0; n < 8; n++) acc[m][n] = 0ull;

    // prologue: chunks 0,1
#pragma unroll
    for (int pc = 0; pc < 2; pc++) {
#pragma unroll
        for (int it = 0; it < 8; it++) {
            int fl = t + 256 * it;                // 0..2047
            int r = fl >> 4, c4 = fl & 15;
            cp_async16(sbase + (uint32_t)((pc * 2048 + r * 16 + ((c4 + (r >> 3)) & 15)) * 16),
                       Xb + r * DD + pc * 64 + c4 * 4);
        }
        CP_COMMIT();
    }

    for (int ch = 0; ch < 16; ch++) {
        if (ch + 2 < 16) {
            int buf = (ch + 2) % 3;
#pragma unroll
            for (int it = 0; it < 8; it++) {
                int fl = t + 256 * it;
                int r = fl >> 4, c4 = fl & 15;
                cp_async16(sbase + (uint32_t)((buf * 2048 + r * 16 + ((c4 + (r >> 3)) & 15)) * 16),
                           Xb + r * DD + (ch + 2) * 64 + c4 * 4);
            }
            CP_COMMIT();
            CP_WAIT(2);
        } else if (ch + 1 < 16) {
            CP_WAIT(1);
        } else {
            CP_WAIT(0);
        }
        __syncthreads();                           // chunk ch visible to all

        const uint32_t cb = sbase + (uint32_t)((ch % 3) * 2048) * 16;
#pragma unroll
        for (int k4 = 0; k4 < 16; k4++) {
            unsigned long long a2[8][2], b2[8][2];
#pragma unroll
            for (int m = 0; m < 8; m++) {
                int r = ty * 8 + m;
                uint32_t sa = cb + (uint32_t)((r * 16 + ((k4 + ty) & 15)) * 16);
                asm volatile("ld.shared.v2.u64 {%0,%1}, [%2];"
                             : "=l"(a2[m][0]), "=l"(a2[m][1]) : "r"(sa));
            }
#pragma unroll
            for (int n = 0; n < 8; n++) {
                int r = tx * 8 + n;
                uint32_t sa = cb + (uint32_t)((r * 16 + ((k4 + tx) & 15)) * 16);
                asm volatile("ld.shared.v2.u64 {%0,%1}, [%2];"
                             : "=l"(b2[n][0]), "=l"(b2[n][1]) : "r"(sa));
            }
#pragma unroll
            for (int m = 0; m < 8; m++)
#pragma unroll
                for (int n = 0; n < 8; n++) {
                    fma2(acc[m][n], a2[m][0], b2[n][0]);
                    fma2(acc[m][n], a2[m][1], b2[n][1]);
                }
        }
        __syncthreads();                           // done reading buf before reuse
    }

    float* Gb = g_G + (size_t)bc * (NV * NV);
#pragma unroll
    for (int m = 0; m < 8; m++) {
        float v[8];
#pragma unroll
        for (int n = 0; n < 8; n++) {
            float lo, hi;
            asm volatile("mov.b64 {%0,%1}, %2;" : "=f"(lo), "=f"(hi) : "l"(acc[m][n]));
            v[n] = lo + hi;
        }
        *(float4*)(Gb + (ty * 8 + m) * NV + tx * 8)     = make_float4(v[0], v[1], v[2], v[3]);
        *(float4*)(Gb + (ty * 8 + m) * NV + tx * 8 + 4) = make_float4(v[4], v[5], v[6], v[7]);
    }
}

// ---------------------------------------------------------------- kernel B
// Recurrence. 128 thr/CTA. L stride 129 (conflict-free for BOTH row reads
// (bank=(t+k)%32) and column reads (bank=(j+t)%32)). G row streamed with
// register prefetch + double-buffered smem row. nn via warp-3 shfl reduce.
__global__ void gs_chol_kernel() {
    extern __shared__ float sm[];
    float* Ls   = sm;                  // 128 x 129
    float* grA  = Ls + NV * 129;       // 2 x 128 (double-buffered G row)
    float* coef = grA + 2 * NV;        // 128
    float* red  = coef + NV;           // 128
    float* nn   = red + NV;            // 128

    const int bc   = blockIdx.x;
    const int t    = threadIdx.x;      // 128
    const int w    = t >> 5;
    const int lane = t & 31;
    const float* Gb = g_G + (size_t)bc * (NV * NV);

    // zero L (16512 floats = 4128 float4)
#pragma unroll
    for (int it = 0; it < 32; it++)
        ((float4*)Ls)[t + 128 * it] = make_float4(0.f, 0.f, 0.f, 0.f);
    if (t < 32) ((float4*)Ls)[4096 + t] = make_float4(0.f, 0.f, 0.f, 0.f);
    nn[t] = 1.f;
    if (t < 32)  // preload G row 1 into buf(1)
        *((float4*)(grA + NV) + t) = ((const float4*)(Gb + NV))[t];
    __syncthreads();
    if (t == 0) { Ls[0] = 1.f; nn[0] = Gb[0]; }
    __syncthreads();

    for (int i = 1; i < NV; i++) {
        const float* gr = grA + (i & 1) * NV;

        // prefetch next G row into regs (latency overlapped with phase A)
        float4 pv;
        if (t < 32 && i + 1 < NV)
            pv = ((const float4*)(Gb + (i + 1) * NV))[t];

        // phase A: s_t = sum_k L[t][k] * G[i][k]
        const float* Lr = Ls + t * 129;
        float s0 = 0.f, s1 = 0.f, s2 = 0.f, s3 = 0.f;
        const int kmax = 32 * (w + 1);             // warp-uniform triangular bound
        for (int k0 = 0; k0 < kmax; k0 += 32) {
#pragma unroll
            for (int k = 0; k < 32; k += 4) {
                s0 += Lr[k0 + k + 0] * gr[k0 + k + 0];
                s1 += Lr[k0 + k + 1] * gr[k0 + k + 1];
                s2 += Lr[k0 + k + 2] * gr[k0 + k + 2];
                s3 += Lr[k0 + k + 3] * gr[k0 + k + 3];
            }
        }
        float s = (s0 + s1) + (s2 + s3);
        float cf = (t < i) ? (s / nn[t]) : 0.f;
        coef[t] = cf;
        red[t]  = cf * s;
        __syncthreads();

        // phase B: L[i][t] = delta(i,t) - sum_j coef[j] * L[j][t]
        float b0 = 0.f, b1 = 0.f, b2 = 0.f, b3 = 0.f;
        const int jmax = (i + 31) & ~31;           // coef[j>=i] == 0
        for (int j0 = 0; j0 < jmax; j0 += 32) {
#pragma unroll
            for (int j = 0; j < 32; j += 4) {
                b0 += coef[j0 + j + 0] * Ls[(j0 + j + 0) * 129 + t];
                b1 += coef[j0 + j + 1] * Ls[(j0 + j + 1) * 129 + t];
                b2 += coef[j0 + j + 2] * Ls[(j0 + j + 2) * 129 + t];
                b3 += coef[j0 + j + 3] * Ls[(j0 + j + 3) * 129 + t];
            }
        }
        Ls[i * 129 + t] = ((t == i) ? 1.f : 0.f) - ((b0 + b1) + (b2 + b3));

        // nn[i] = G[i][i] - sum_j red[j]  (warp 3, parallel reduce)
        if (w == 3) {
            float rv = (red[lane] + red[lane + 32]) + (red[lane + 64] + red[lane + 96]);
            rv += __shfl_xor_sync(0xffffffffu, rv, 16);
            rv += __shfl_xor_sync(0xffffffffu, rv, 8);
            rv += __shfl_xor_sync(0xffffffffu, rv, 4);
            rv += __shfl_xor_sync(0xffffffffu, rv, 2);
            rv += __shfl_xor_sync(0xffffffffu, rv, 1);
            if (lane == 0) nn[i] = gr[i] - rv;
        }
        // stash prefetched row into the other buffer
        if (t < 32 && i + 1 < NV)
            *((float4*)(grA + ((i + 1) & 1) * NV) + t) = pv;
        __syncthreads();
    }

    float* Lb = g_L + (size_t)bc * (NV * NV);
#pragma unroll 4
    for (int it = 0; it < 32; it++) {
        int fl = t + 128 * it;                     // float4 index 0..4095
        int r = fl >> 5, k4 = fl & 31;
        const float* src = Ls + r * 129 + k4 * 4;
        ((float4*)Lb)[fl] = make_float4(src[0], src[1], src[2], src[3]);
    }
}

// ---------------------------------------------------------------- kernel C
// Q = L @ Xchunk (triangular), f32x2 FMA (pairs over n), then column
// sum-of-squares over N, scale, store. blockIdx = bc*8 + dchunk.
__global__ void gs_apply_kernel(const float* __restrict__ X, float* __restrict__ out) {
    extern __shared__ float smf[];
    float4* Ls4 = (float4*)smf;            // 128 x 32 f4 swizzled
    float*  Xc  = smf + NV * NV;           // 128 k x 128 d
    float*  rn  = Xc + NV * NV;            // 128

    const int bc = blockIdx.x >> 3;
    const int dc = blockIdx.x & 7;
    const int t  = threadIdx.x;
    const int tx = t & 15;
    const int ty = t >> 4;
    const uint32_t sbase = (uint32_t)__cvta_generic_to_shared(smf);

    const float* Xb = X + (size_t)bc * (NV * DD) + dc * 128;
    const float* Lb = g_L + (size_t)bc * (NV * NV);

#pragma unroll
    for (int it = 0; it < 16; it++) {
        int fl = t + 256 * it;
        int r = fl >> 5, k4 = fl & 31;
        float4 v = ((const float4*)Lb)[r * 32 + k4];
        Ls4[r * 32 + ((k4 + (r >> 3)) & 31)] = v;
    }
#pragma unroll
    for (int it = 0; it < 16; it++) {
        int fl = t + 256 * it;
        int r = fl >> 5, c4 = fl & 31;
        *(float4*)(Xc + r * 128 + c4 * 4) = *(const float4*)(Xb + r * DD + c4 * 4);
    }
    __syncthreads();

    unsigned long long acc2[8][4];
#pragma unroll
    for (int m = 0; m < 8; m++)
#pragma unroll
        for (int p = 0; p < 4; p++) acc2[m][p] = 0ull;

    const int kmax4 = 2 * ty + 2;          // rows ty*8..ty*8+7 need k <= ty*8+7
    for (int k4 = 0; k4 < kmax4; k4++) {
        float4 a4[8];
#pragma unroll
        for (int m = 0; m < 8; m++) a4[m] = Ls4[(ty * 8 + m) * 32 + ((k4 + ty) & 31)];
#pragma unroll
        for (int kk = 0; kk < 4; kk++) {
            unsigned long long bp[4];
            uint32_t sa = sbase + (uint32_t)(NV * NV * 4) +
                          (uint32_t)(((k4 * 4 + kk) * 128 + tx * 8) * 4);
            asm volatile("ld.shared.v2.u64 {%0,%1}, [%2];"
                         : "=l"(bp[0]), "=l"(bp[1]) : "r"(sa));
            asm volatile("ld.shared.v2.u64 {%0,%1}, [%2];"
                         : "=l"(bp[2]), "=l"(bp[3]) : "r"(sa + 16));
#pragma unroll
            for (int m = 0; m < 8; m++) {
                float av = (kk == 0) ? a4[m].x : (kk == 1) ? a4[m].y
                         : (kk == 2) ? a4[m].z : a4[m].w;
                unsigned long long ap;
                asm volatile("mov.b64 %0, {%1,%1};" : "=l"(ap) : "f"(av));
                fma2(acc2[m][0], ap, bp[0]);
                fma2(acc2[m][1], ap, bp[1]);
                fma2(acc2[m][2], ap, bp[2]);
                fma2(acc2[m][3], ap, bp[3]);
            }
        }
    }
    __syncthreads();                        // everyone done reading Ls4

    float* Qs = smf;                        // reuse L region as Q staging
#pragma unroll
    for (int m = 0; m < 8; m++) {
        float v[8];
#pragma unroll
        for (int p = 0; p < 4; p++) {
            float lo, hi;
            asm volatile("mov.b64 {%0,%1}, %2;" : "=f"(lo), "=f"(hi) : "l"(acc2[m][p]));
            v[2 * p] = lo; v[2 * p + 1] = hi;
        }
        *(float4*)(Qs + (ty * 8 + m) * 128 + tx * 8)     = make_float4(v[0], v[1], v[2], v[3]);
        *(float4*)(Qs + (ty * 8 + m) * 128 + tx * 8 + 4) = make_float4(v[4], v[5], v[6], v[7]);
    }
    __syncthreads();

    if (t < 128) {
        float s = 0.f;
#pragma unroll 4
        for (int i = 0; i < 128; i++) { float q = Qs[i * 128 + t]; s += q * q; }
        rn[t] = rsqrtf(s);
    }
    __syncthreads();

    float* ob = out + (size_t)bc * (NV * DD) + dc * 128;
#pragma unroll
    for (int it = 0; it < 16; it++) {
        int fl = t + 256 * it;
        int r = fl >> 5, c4 = fl & 31;
        float4 q = *(float4*)(Qs + r * 128 + c4 * 4);
        q.x *= rn[c4 * 4 + 0];
        q.y *= rn[c4 * 4 + 1];
        q.z *= rn[c4 * 4 + 2];
        q.w *= rn[c4 * 4 + 3];
        *(float4*)(ob + r * DD + c4 * 4) = q;
    }
}

// ---------------------------------------------------------------- launcher
extern "C" void kernel_launch(void* const* d_in, const int* in_sizes, int n_in,
                              void* d_out, int out_size) {
    const float* x = (const float*)d_in[0];
    float* out = (float*)d_out;

    const int smA = 3 * 2048 * (int)sizeof(float4);                     // 98304
    const int smB = (NV * 129 + 5 * NV) * (int)sizeof(float);           // 68608
    const int smC = (NV * NV * 2 + NV) * (int)sizeof(float);            // 131584

    cudaFuncSetAttribute(gs_gram_kernel,  cudaFuncAttributeMaxDynamicSharedMemorySize, smA);
    cudaFuncSetAttribute(gs_chol_kernel,  cudaFuncAttributeMaxDynamicSharedMemorySize, smB);
    cudaFuncSetAttribute(gs_apply_kernel, cudaFuncAttributeMaxDynamicSharedMemorySize, smC);

    gs_gram_kernel<<<NBC, 256, smA>>>(x);
    gs_chol_kernel<<<NBC, 128, smB>>>();
    gs_apply_kernel<<<NBC * 8, 256, smC>>>(x, out);
}